// round 9
// baseline (speedup 1.0000x reference)
#include <cuda_runtime.h>
#include <cuda_bf16.h>

// result(row) = sum over 28 chunk-pair tables T_(A,B)[nib_A][nib_B],
// 32 bits -> 8 nibbles. All 528 order<=2 terms folded into the tables.
// Eval: lane-transposed coalesced loads (all 8 batched for MLP=8) +
// shuffle nibble packing; 512-thr blocks, 2 blocks/SM.

#define NPAIRS 28
#define TABSZ (NPAIRS * 256)   // 7168 floats = 28 KB

__device__ float g_tab[TABSZ];

// variables index for pair (i,j), i<j (itertools.combinations order)
__device__ __forceinline__ int pair_v(int i, int j) {
    return 32 + i * 31 - (i * (i - 1)) / 2 + (j - i - 1);
}

__global__ void KOBE_76948634075865_precompute(const float* __restrict__ vars) {
    int p = blockIdx.x;          // chunk-pair index 0..27
    int t = threadIdx.x;         // entry index 0..255
    int a = t >> 4;              // nibble value of chunk A
    int b = t & 15;              // nibble value of chunk B

    // decode p -> (A,B), A<B over 8 chunks
    int A = 0, rem = p, cnt = 7;
    while (rem >= cnt) { rem -= cnt; cnt--; A++; }
    int B = A + 1 + rem;

    float sa[4], sb[4];
#pragma unroll
    for (int k = 0; k < 4; k++) {
        sa[k] = 1.0f - 2.0f * (float)((a >> k) & 1);
        sb[k] = 1.0f - 2.0f * (float)((b >> k) & 1);
    }

    float acc = 0.0f;

#pragma unroll
    for (int i2 = 0; i2 < 4; i2++) {
        int i = 4 * A + i2;
#pragma unroll
        for (int j2 = 0; j2 < 4; j2++) {
            int j = 4 * B + j2;
            acc += vars[pair_v(i, j)] * sa[i2] * sb[j2];
        }
    }

    if (B == 7) {
#pragma unroll
        for (int i2 = 0; i2 < 4; i2++) {
            int i = 4 * A + i2;
            acc += vars[i] * sa[i2];
#pragma unroll
            for (int j2 = i2 + 1; j2 < 4; j2++) {
                int j = 4 * A + j2;
                acc += vars[pair_v(i, j)] * sa[i2] * sa[j2];
            }
        }
        if (A == 6) {
#pragma unroll
            for (int i2 = 0; i2 < 4; i2++) {
                int i = 28 + i2;
                acc += vars[i] * sb[i2];
#pragma unroll
                for (int j2 = i2 + 1; j2 < 4; j2++) {
                    int j = 28 + j2;
                    acc += vars[pair_v(i, j)] * sb[i2] * sb[j2];
                }
            }
        }
    }

    g_tab[p * 256 + a * 16 + b] = acc;
}

__global__ __launch_bounds__(512, 2) void KOBE_76948634075865_eval(
    const int4* __restrict__ bits, float* __restrict__ out, int batch) {
    __shared__ float tab[TABSZ];
    int tid = threadIdx.x;
    int warp = tid >> 5, lane = tid & 31;
    int grp = lane >> 3;           // 8-lane group (0..3) within warp
    int c = lane & 7;              // this lane's chunk slot

    // Kick off the table fill LDGs first (L2 hits, independent of row loads)
    {
        const float4* src = (const float4*)g_tab;
        float4* dst = (float4*)tab;
        for (int j = tid; j < TABSZ / 4; j += 512) dst[j] = src[j];
    }

    int base = blockIdx.x * 512 + warp * 32;    // first row of this warp
    const int4* p = bits + (size_t)base * 8;
    bool full = (base + 32 <= batch);

    // Batch ALL 8 lane-transposed loads before any shuffle: 8 independent
    // LDG.128 in flight per thread (MLP=8). Each covers 512 contiguous bytes
    // per warp instruction.
    int4 xs[8];
#pragma unroll
    for (int i = 0; i < 8; i++) {
        int lin = i * 32 + lane;
        if (full || base + (lin >> 3) < batch) xs[i] = p[lin];
        else xs[i] = make_int4(0, 0, 0, 0);
    }

    // Butterfly-OR pack: iteration i produces the packed nibbles of rows
    // base+4i+0..3; lane (grp,c) keeps the word at i == c -> row base+4c+grp.
    unsigned packed = 0;
#pragma unroll
    for (int i = 0; i < 8; i++) {
        int nib = xs[i].x + 2 * xs[i].y + 4 * xs[i].z + 8 * xs[i].w;
        unsigned v = (unsigned)nib << (4 * c);
        v |= __shfl_xor_sync(0xffffffffu, v, 1);
        v |= __shfl_xor_sync(0xffffffffu, v, 2);
        v |= __shfl_xor_sync(0xffffffffu, v, 4);
        if (i == c) packed = v;
    }
    __syncthreads();

    int myrow = base + 4 * c + grp;
    if (myrow >= batch) return;

    int n[8];
#pragma unroll
    for (int k = 0; k < 8; k++) n[k] = (packed >> (4 * k)) & 15;

    float acc0 = 0.f, acc1 = 0.f, acc2 = 0.f, acc3 = 0.f;
    int idx = 0;
#pragma unroll
    for (int A = 0; A < 8; A++) {
#pragma unroll
        for (int B = A + 1; B < 8; B++) {
            float v = tab[idx * 256 + n[A] * 16 + n[B]];
            if ((idx & 3) == 0)      acc0 += v;
            else if ((idx & 3) == 1) acc1 += v;
            else if ((idx & 3) == 2) acc2 += v;
            else                     acc3 += v;
            idx++;
        }
    }
    out[myrow] = (acc0 + acc1) + (acc2 + acc3);
}

extern "C" void kernel_launch(void* const* d_in, const int* in_sizes, int n_in,
                              void* d_out, int out_size) {
    const int4* bits = (const int4*)d_in[0];    // [BATCH, 32] int32
    const float* vars = (const float*)d_in[1];  // [528] float32
    int batch = in_sizes[0] / 32;
    float* out = (float*)d_out;

    KOBE_76948634075865_precompute<<<NPAIRS, 256>>>(vars);

    int blocks = (batch + 511) / 512;
    KOBE_76948634075865_eval<<<blocks, 512>>>(bits, out, batch);
}